// round 1
// baseline (speedup 1.0000x reference)
#include <cuda_runtime.h>
#include <float.h>

#define N_SAMPLES 8192
#define DIM 128
#define N_EMBED 10000
#define N_EMBED_PAD 10240
#define TM 64
#define TN 256
#define THREADS 256
#define AS_STRIDE 68   // 64 + 4 pad, keeps float4 alignment (68*4 % 16 == 0)

// Scratch: padded cluster norms. Entries >= N_EMBED are -1e30 so they never win argmax.
__device__ float g_cnorm[N_EMBED_PAD];

__global__ void cnorm_kernel(const float* __restrict__ cm) {
    int j = blockIdx.x * blockDim.x + threadIdx.x;
    if (j >= N_EMBED_PAD) return;
    if (j < N_EMBED) {
        float s = 0.f;
#pragma unroll 8
        for (int d = 0; d < DIM; d++) {
            float v = cm[d * N_EMBED + j];
            s += v * v;
        }
        g_cnorm[j] = s;
    } else {
        g_cnorm[j] = -1e30f;
    }
}

// Fused GEMM + argmax + gather + MSE.
// A: inputs [N_SAMPLES, DIM] row-major. Bm: cluster_mean [DIM, N_EMBED] row-major.
// out layout: [quantize N*DIM][index N][diff N], all float32.
__global__ __launch_bounds__(THREADS, 1)
void quantize_kernel(const float* __restrict__ A,
                     const float* __restrict__ Bm,
                     float* __restrict__ out) {
    extern __shared__ float smf[];
    float* As = smf;                       // [DIM][AS_STRIDE], holds -2*x transposed
    float* Bs = smf + DIM * AS_STRIDE;     // [DIM][TN]

    const int tid  = threadIdx.x;
    const int lane = tid & 31;
    const int sy   = tid >> 5;             // warp id 0..7 -> sample group
    const int m0   = blockIdx.x * TM;

    // Load A tile, transpose into smem with -2 folded in.
    for (int i = tid; i < TM * (DIM / 4); i += THREADS) {
        int m  = i >> 5;       // 0..63
        int k4 = i & 31;       // 0..31
        float4 v = *(const float4*)&A[(m0 + m) * DIM + k4 * 4];
        As[(k4 * 4 + 0) * AS_STRIDE + m] = -2.f * v.x;
        As[(k4 * 4 + 1) * AS_STRIDE + m] = -2.f * v.y;
        As[(k4 * 4 + 2) * AS_STRIDE + m] = -2.f * v.z;
        As[(k4 * 4 + 3) * AS_STRIDE + m] = -2.f * v.w;
    }

    float best[8];
    int   bestj[8];
#pragma unroll
    for (int i = 0; i < 8; i++) { best[i] = -FLT_MAX; bestj[i] = 0; }

    for (int jc = 0; jc < N_EMBED_PAD; jc += TN) {
        __syncthreads();  // Bs reuse safe; also covers initial As availability
        // Load B chunk [DIM][TN]; zero-fill beyond N_EMBED (N_EMBED % 4 == 0).
        for (int i = tid; i < DIM * (TN / 4); i += THREADS) {
            int r  = i >> 6;   // 0..127
            int c4 = i & 63;   // 0..63
            int j  = jc + c4 * 4;
            float4 v;
            if (j + 3 < N_EMBED) {
                v = *(const float4*)&Bm[r * N_EMBED + j];
            } else {
                v.x = v.y = v.z = v.w = 0.f;
            }
            *(float4*)&Bs[r * TN + c4 * 4] = v;
        }
        __syncthreads();

        float acc[8][8];
#pragma unroll
        for (int i = 0; i < 8; i++)
#pragma unroll
            for (int c = 0; c < 8; c++) acc[i][c] = 0.f;

        const float* Ap = As + 8 * sy;     // warp-uniform -> broadcast reads
        const float* Bp = Bs + 8 * lane;

#pragma unroll 4
        for (int k = 0; k < DIM; k++) {
            float4 a0 = *(const float4*)&Ap[k * AS_STRIDE];
            float4 a1 = *(const float4*)&Ap[k * AS_STRIDE + 4];
            float4 b0 = *(const float4*)&Bp[k * TN];
            float4 b1 = *(const float4*)&Bp[k * TN + 4];
            float a[8] = {a0.x, a0.y, a0.z, a0.w, a1.x, a1.y, a1.z, a1.w};
            float b[8] = {b0.x, b0.y, b0.z, b0.w, b1.x, b1.y, b1.z, b1.w};
#pragma unroll
            for (int i = 0; i < 8; i++)
#pragma unroll
                for (int c = 0; c < 8; c++)
                    acc[i][c] += a[i] * b[c];
        }

        // Running argmax of val = |c_j|^2 - 2 x.c_j  (== dist up to per-row const).
        // Strict '>' + ascending j scan preserves first-occurrence semantics.
        const int jbase = jc + 8 * lane;
#pragma unroll
        for (int c = 0; c < 8; c++) {
            float cn = g_cnorm[jbase + c];
#pragma unroll
            for (int i = 0; i < 8; i++) {
                float val = cn + acc[i][c];
                if (val > best[i]) { best[i] = val; bestj[i] = jbase + c; }
            }
        }
    }

    // Cross-lane argmax reduce (tie-break: smaller index, matching jnp.argmax).
#pragma unroll
    for (int i = 0; i < 8; i++) {
        float v = best[i];
        int   bj = bestj[i];
#pragma unroll
        for (int off = 16; off > 0; off >>= 1) {
            float v2 = __shfl_xor_sync(0xFFFFFFFFu, v, off);
            int   j2 = __shfl_xor_sync(0xFFFFFFFFu, bj, off);
            if (v2 > v || (v2 == v && j2 < bj)) { v = v2; bj = j2; }
        }
        bestj[i] = bj;  // all lanes now hold the final index for sample i
    }

    // Epilogue: gather quantize vector, write index + per-row MSE.
    float* out_q    = out;
    float* out_idx  = out + N_SAMPLES * DIM;
    float* out_diff = out_idx + N_SAMPLES;

#pragma unroll
    for (int i = 0; i < 8; i++) {
        const int s = m0 + 8 * sy + i;
        const int j = bestj[i];
        const int mloc = 8 * sy + i;
        float sum = 0.f;
        for (int d = lane; d < DIM; d += 32) {
            float q = Bm[d * N_EMBED + j];
            float x = -0.5f * As[d * AS_STRIDE + mloc];
            out_q[s * DIM + d] = q;
            float t = x - q;
            sum += t * t;
        }
#pragma unroll
        for (int off = 16; off > 0; off >>= 1)
            sum += __shfl_xor_sync(0xFFFFFFFFu, sum, off);
        if (lane == 0) {
            out_idx[s]  = (float)j;
            out_diff[s] = sum * (1.0f / DIM);
        }
    }
}

extern "C" void kernel_launch(void* const* d_in, const int* in_sizes, int n_in,
                              void* d_out, int out_size) {
    const float* A  = (const float*)d_in[0];   // inputs [8192,128]
    const float* Bm = (const float*)d_in[1];   // cluster_mean [128,10000]
    if (n_in >= 2 && in_sizes[0] == DIM * N_EMBED) {  // defensive: swap if order differs
        const float* t = A; A = Bm; Bm = t;
    }
    float* out = (float*)d_out;

    cnorm_kernel<<<N_EMBED_PAD / 256, 256>>>(Bm);

    const int smem_bytes = (DIM * AS_STRIDE + DIM * TN) * (int)sizeof(float);
    static int attr_set = 0;
    if (!attr_set) {
        cudaFuncSetAttribute(quantize_kernel,
                             cudaFuncAttributeMaxDynamicSharedMemorySize, smem_bytes);
        attr_set = 1;
    }
    quantize_kernel<<<N_SAMPLES / TM, THREADS, smem_bytes>>>(A, Bm, out);
}

// round 2
// speedup vs baseline: 1.2353x; 1.2353x over previous
#include <cuda_runtime.h>
#include <float.h>

#define N_SAMPLES 8192
#define DIM 128
#define N_EMBED 10000
#define TN 128
#define NCHUNK 80            // 80*128 = 10240 padded cluster count
#define N_EMBED_PAD (NCHUNK*TN)
#define TM 64
#define THREADS 256

typedef unsigned long long u64;

// Padded cluster norms; entries >= N_EMBED are -1e30 so they never win argmax.
__device__ float g_cnorm[N_EMBED_PAD];

__global__ void cnorm_kernel(const float* __restrict__ cm) {
    int j = blockIdx.x * blockDim.x + threadIdx.x;
    if (j >= N_EMBED_PAD) return;
    if (j < N_EMBED) {
        float s = 0.f;
#pragma unroll 8
        for (int d = 0; d < DIM; d++) {
            float v = cm[d * N_EMBED + j];
            s += v * v;
        }
        g_cnorm[j] = s;
    } else {
        g_cnorm[j] = -1e30f;
    }
}

__device__ __forceinline__ void fma2(u64& d, u64 a, u64 b) {
    asm("fma.rn.f32x2 %0, %1, %2, %0;" : "+l"(d) : "l"(a), "l"(b));
}
__device__ __forceinline__ u64 dup2(float v) {
    u64 r; asm("mov.b64 %0, {%1, %1};" : "=l"(r) : "f"(v)); return r;
}
__device__ __forceinline__ float lo_f(u64 v) { return __uint_as_float((unsigned)v); }
__device__ __forceinline__ float hi_f(u64 v) { return __uint_as_float((unsigned)(v >> 32)); }
__device__ __forceinline__ unsigned smem_u32(const void* p) {
    return (unsigned)__cvta_generic_to_shared(p);
}
__device__ __forceinline__ void cp16(unsigned dst, const void* src, int sz) {
    asm volatile("cp.async.cg.shared.global [%0], [%1], 16, %2;"
                 :: "r"(dst), "l"(src), "r"(sz));
}

// Fused GEMM(-2x.c) + argmax(|c|^2 - 2x.c) + gather + MSE.
// A: [N_SAMPLES, DIM] row-major. Bm: [DIM, N_EMBED] row-major.
// out: [quantize N*DIM][index N][diff N] float32.
__global__ __launch_bounds__(THREADS, 1)
void quantize_kernel(const float* __restrict__ A,
                     const float* __restrict__ Bm,
                     float* __restrict__ out) {
    extern __shared__ float smf[];
    float* As = smf;                 // [DIM][TM]  (transposed, holds -2*x)  32KB
    float* Bs = smf + DIM * TM;      // 2 x [DIM][TN]                       128KB

    const int tid  = threadIdx.x;
    const int lane = tid & 31;
    const int sy   = tid >> 5;       // warp -> 8-sample group
    const int m0   = blockIdx.x * TM;

    // A tile: transpose into smem with -2 folded in. Mapping chosen so STS is
    // conflict-free (lanes walk m); LDG is strided but A is tiny (32KB/block).
    for (int i = tid; i < TM * (DIM / 4); i += THREADS) {
        int k4 = i >> 6;             // 0..31
        int m  = i & 63;             // 0..63
        float4 v = *(const float4*)&A[(m0 + m) * DIM + 4 * k4];
        As[(4 * k4 + 0) * TM + m] = -2.f * v.x;
        As[(4 * k4 + 1) * TM + m] = -2.f * v.y;
        As[(4 * k4 + 2) * TM + m] = -2.f * v.z;
        As[(4 * k4 + 3) * TM + m] = -2.f * v.w;
    }

    // Issue B chunk t into buffer buf via cp.async (zero-fill past N_EMBED).
    auto issueB = [&](int t, int buf) {
        const int j0 = t * TN;
        float* dst = Bs + buf * DIM * TN;
        for (int i = tid; i < DIM * (TN / 4); i += THREADS) {  // 16 iters
            int r  = i >> 5;        // 0..127
            int c4 = i & 31;        // 0..31
            int j  = j0 + 4 * c4;
            const float* src = (j < N_EMBED) ? (Bm + (size_t)r * N_EMBED + j) : Bm;
            cp16(smem_u32(dst + r * TN + 4 * c4), src, (j < N_EMBED) ? 16 : 0);
        }
        asm volatile("cp.async.commit_group;");
    };

    issueB(0, 0);
    issueB(1, 1);

    float best[8];
    int   bestj[8];
#pragma unroll
    for (int i = 0; i < 8; i++) { best[i] = -FLT_MAX; bestj[i] = 0; }

    const float* Ap = As + 8 * sy;   // warp-uniform -> broadcast LDS

    for (int t = 0; t < NCHUNK; t++) {
        if (t < NCHUNK - 1) asm volatile("cp.async.wait_group 1;");
        else                asm volatile("cp.async.wait_group 0;");
        __syncthreads();             // chunk t resident in both halves' view

        const float* Bp = Bs + (t & 1) * DIM * TN + 4 * lane;

        u64 acc[4][4];               // [sample-pair][col]; lo = even sample
#pragma unroll
        for (int p = 0; p < 4; p++)
#pragma unroll
            for (int c = 0; c < 4; c++) acc[p][c] = 0ull;

#pragma unroll 8
        for (int k = 0; k < DIM; k++) {
            const ulonglong2* ap = (const ulonglong2*)(Ap + k * TM);
            ulonglong2 a01 = ap[0];             // pairs (m0,m1),(m2,m3)
            ulonglong2 a23 = ap[1];             // pairs (m4,m5),(m6,m7)
            float4 b4 = *(const float4*)(Bp + k * TN);
            u64 b0 = dup2(b4.x), b1 = dup2(b4.y), b2 = dup2(b4.z), b3 = dup2(b4.w);
            fma2(acc[0][0], a01.x, b0); fma2(acc[0][1], a01.x, b1);
            fma2(acc[0][2], a01.x, b2); fma2(acc[0][3], a01.x, b3);
            fma2(acc[1][0], a01.y, b0); fma2(acc[1][1], a01.y, b1);
            fma2(acc[1][2], a01.y, b2); fma2(acc[1][3], a01.y, b3);
            fma2(acc[2][0], a23.x, b0); fma2(acc[2][1], a23.x, b1);
            fma2(acc[2][2], a23.x, b2); fma2(acc[2][3], a23.x, b3);
            fma2(acc[3][0], a23.y, b0); fma2(acc[3][1], a23.y, b1);
            fma2(acc[3][2], a23.y, b2); fma2(acc[3][3], a23.y, b3);
        }

        // Running argmax of |c_j|^2 - 2 x.c_j. Ascending j scan + strict '>'
        // preserves first-occurrence semantics (matches jnp.argmax).
        const int jbase = t * TN + 4 * lane;
        float4 cn4 = *(const float4*)&g_cnorm[jbase];
        float cna[4] = {cn4.x, cn4.y, cn4.z, cn4.w};
#pragma unroll
        for (int c = 0; c < 4; c++) {
#pragma unroll
            for (int p = 0; p < 4; p++) {
                float vlo = lo_f(acc[p][c]) + cna[c];
                float vhi = hi_f(acc[p][c]) + cna[c];
                int slo = 2 * p, shi = 2 * p + 1;
                if (vlo > best[slo]) { best[slo] = vlo; bestj[slo] = jbase + c; }
                if (vhi > best[shi]) { best[shi] = vhi; bestj[shi] = jbase + c; }
            }
        }

        __syncthreads();             // all warps done with buffer (t&1)
        if (t + 2 < NCHUNK) issueB(t + 2, t & 1);
    }

    // Cross-lane argmax reduce (tie-break: smaller index).
#pragma unroll
    for (int i = 0; i < 8; i++) {
        float v  = best[i];
        int   bj = bestj[i];
#pragma unroll
        for (int off = 16; off > 0; off >>= 1) {
            float v2 = __shfl_xor_sync(0xFFFFFFFFu, v, off);
            int   j2 = __shfl_xor_sync(0xFFFFFFFFu, bj, off);
            if (v2 > v || (v2 == v && j2 < bj)) { v = v2; bj = j2; }
        }
        bestj[i] = bj;               // all lanes hold final index
    }

    // Epilogue: gather quantize vector, write index + per-row MSE.
    float* out_q    = out;
    float* out_idx  = out + N_SAMPLES * DIM;
    float* out_diff = out_idx + N_SAMPLES;

#pragma unroll
    for (int i = 0; i < 8; i++) {
        const int s    = m0 + 8 * sy + i;
        const int j    = bestj[i];
        const int mloc = 8 * sy + i;
        float sum = 0.f;
        for (int d = lane; d < DIM; d += 32) {
            float q = Bm[d * N_EMBED + j];
            float x = -0.5f * As[d * TM + mloc];
            out_q[s * DIM + d] = q;
            float tdiff = x - q;
            sum += tdiff * tdiff;
        }
#pragma unroll
        for (int off = 16; off > 0; off >>= 1)
            sum += __shfl_xor_sync(0xFFFFFFFFu, sum, off);
        if (lane == 0) {
            out_idx[s]  = (float)j;
            out_diff[s] = sum * (1.0f / DIM);
        }
    }
}

extern "C" void kernel_launch(void* const* d_in, const int* in_sizes, int n_in,
                              void* d_out, int out_size) {
    const float* A  = (const float*)d_in[0];   // inputs [8192,128]
    const float* Bm = (const float*)d_in[1];   // cluster_mean [128,10000]
    if (n_in >= 2 && in_sizes[0] == DIM * N_EMBED) {  // defensive order check
        const float* t = A; A = Bm; Bm = t;
    }
    float* out = (float*)d_out;

    cnorm_kernel<<<N_EMBED_PAD / 256, 256>>>(Bm);

    const int smem_bytes = (DIM * TM + 2 * DIM * TN) * (int)sizeof(float); // 160KB
    cudaFuncSetAttribute(quantize_kernel,
                         cudaFuncAttributeMaxDynamicSharedMemorySize, smem_bytes);
    quantize_kernel<<<N_SAMPLES / TM, THREADS, smem_bytes>>>(A, Bm, out);
}

// round 4
// speedup vs baseline: 1.2733x; 1.0308x over previous
#include <cuda_runtime.h>
#include <float.h>
#include <stdint.h>

#define N_SAMPLES 8192
#define DIM 128
#define N_EMBED 10000
#define N_EMBED_PAD 10240
#define TN 128
#define TM 64
#define THREADS 256
#define NSLICE 8
#define SLICE_W 1280          // clusters per slice
#define NCH 10                // chunks of TN per slice

typedef unsigned long long u64;

// Padded cluster norms; entries >= N_EMBED are -1e30 so they never win argmax.
__device__ float g_cnorm[N_EMBED_PAD];
// Per-sample packed (encoded_val << 32 | ~j); atomicMax-merged across slices.
__device__ u64 g_best[N_SAMPLES];

__global__ void cnorm_kernel(const float* __restrict__ cm) {
    int j = blockIdx.x * blockDim.x + threadIdx.x;
    if (j < N_SAMPLES) g_best[j] = 0ull;
    if (j >= N_EMBED_PAD) return;
    if (j < N_EMBED) {
        float s = 0.f;
#pragma unroll 8
        for (int d = 0; d < DIM; d++) {
            float v = cm[d * N_EMBED + j];
            s += v * v;
        }
        g_cnorm[j] = s;
    } else {
        g_cnorm[j] = -1e30f;
    }
}

__device__ __forceinline__ void fma2(u64& d, u64 a, u64 b) {
    asm("fma.rn.f32x2 %0, %1, %2, %0;" : "+l"(d) : "l"(a), "l"(b));
}
__device__ __forceinline__ u64 dup2(float v) {
    u64 r; asm("mov.b64 %0, {%1, %1};" : "=l"(r) : "f"(v)); return r;
}
__device__ __forceinline__ float lo_f(u64 v) { return __uint_as_float((unsigned)v); }
__device__ __forceinline__ float hi_f(u64 v) { return __uint_as_float((unsigned)(v >> 32)); }
__device__ __forceinline__ unsigned smem_u32(const void* p) {
    return (unsigned)__cvta_generic_to_shared(p);
}
__device__ __forceinline__ void cp16(unsigned dst, const void* src, int sz) {
    asm volatile("cp.async.cg.shared.global [%0], [%1], 16, %2;"
                 :: "r"(dst), "l"(src), "r"(sz));
}
// Order-preserving encode: larger val -> larger u64; equal val -> smaller j wins.
__device__ __forceinline__ u64 enc_best(float v, int j) {
    unsigned b = __float_as_uint(v);
    b = ((int)b < 0) ? ~b : (b | 0x80000000u);
    return ((u64)b << 32) | (unsigned)(~j);
}

// Fused GEMM(-2x.c, biased by |c|^2) + argmax, one (m-tile, j-slice) per CTA.
__global__ __launch_bounds__(THREADS, 1)
void quantize_kernel(const float* __restrict__ A,
                     const float* __restrict__ Bm) {
    extern __shared__ float smf[];
    float* As = smf;                 // [DIM][TM]  transposed, holds -2*x   32KB
    float* Bs = smf + DIM * TM;      // 3 x [DIM][TN] ring                 192KB

    const int tid  = threadIdx.x;
    const int lane = tid & 31;
    const int sy   = tid >> 5;       // warp -> 8-sample group
    const int mt   = blockIdx.x & 127;
    const int sl   = blockIdx.x >> 7;
    const int m0   = mt * TM;
    const int j00  = sl * SLICE_W;

    // A tile: transpose into smem with -2 folded in.
    for (int i = tid; i < TM * (DIM / 4); i += THREADS) {
        int k4 = i >> 6;             // 0..31
        int m  = i & 63;             // 0..63
        float4 v = *(const float4*)&A[(m0 + m) * DIM + 4 * k4];
        As[(4 * k4 + 0) * TM + m] = -2.f * v.x;
        As[(4 * k4 + 1) * TM + m] = -2.f * v.y;
        As[(4 * k4 + 2) * TM + m] = -2.f * v.z;
        As[(4 * k4 + 3) * TM + m] = -2.f * v.w;
    }

    auto issueB = [&](int t) {
        const int j0 = j00 + t * TN;
        float* dst = Bs + (t % 3) * DIM * TN;
        for (int i = tid; i < DIM * (TN / 4); i += THREADS) {  // 16 iters
            int r  = i >> 5;        // 0..127
            int c4 = i & 31;        // 0..31
            int j  = j0 + 4 * c4;
            const float* src = (j < N_EMBED) ? (Bm + (size_t)r * N_EMBED + j) : Bm;
            cp16(smem_u32(dst + r * TN + 4 * c4), src, (j < N_EMBED) ? 16 : 0);
        }
        asm volatile("cp.async.commit_group;");
    };

    issueB(0);
    issueB(1);

    float best[8];
    int   bestj[8];
#pragma unroll
    for (int i = 0; i < 8; i++) { best[i] = -FLT_MAX; bestj[i] = 0; }

    const float* Ap = As + 8 * sy;   // warp-uniform -> broadcast LDS

    for (int t = 0; t < NCH; t++) {
        if (t < NCH - 1) asm volatile("cp.async.wait_group 1;");
        else             asm volatile("cp.async.wait_group 0;");
        __syncthreads();             // chunk t resident; slot (t+2)%3 reusable
        if (t + 2 < NCH) issueB(t + 2);

        const float* Bp = Bs + (t % 3) * DIM * TN + 4 * lane;
        const int jbase = j00 + t * TN + 4 * lane;

        // acc starts at |c_j|^2 (same for both packed samples of a pair).
        float4 cn4 = *(const float4*)&g_cnorm[jbase];
        u64 cc[4] = {dup2(cn4.x), dup2(cn4.y), dup2(cn4.z), dup2(cn4.w)};
        u64 acc[4][4];
#pragma unroll
        for (int p = 0; p < 4; p++)
#pragma unroll
            for (int c = 0; c < 4; c++) acc[p][c] = cc[c];

#pragma unroll 8
        for (int k = 0; k < DIM; k++) {
            const ulonglong2* ap = (const ulonglong2*)(Ap + k * TM);
            ulonglong2 a01 = ap[0];             // pairs (m0,m1),(m2,m3)
            ulonglong2 a23 = ap[1];             // pairs (m4,m5),(m6,m7)
            float4 b4 = *(const float4*)(Bp + k * TN);
            u64 b0 = dup2(b4.x), b1 = dup2(b4.y), b2 = dup2(b4.z), b3 = dup2(b4.w);
            fma2(acc[0][0], a01.x, b0); fma2(acc[0][1], a01.x, b1);
            fma2(acc[0][2], a01.x, b2); fma2(acc[0][3], a01.x, b3);
            fma2(acc[1][0], a01.y, b0); fma2(acc[1][1], a01.y, b1);
            fma2(acc[1][2], a01.y, b2); fma2(acc[1][3], a01.y, b3);
            fma2(acc[2][0], a23.x, b0); fma2(acc[2][1], a23.x, b1);
            fma2(acc[2][2], a23.x, b2); fma2(acc[2][3], a23.x, b3);
            fma2(acc[3][0], a23.y, b0); fma2(acc[3][1], a23.y, b1);
            fma2(acc[3][2], a23.y, b2); fma2(acc[3][3], a23.y, b3);
        }

        // Running argmax. Ascending j + strict '>' keeps first-occurrence.
#pragma unroll
        for (int c = 0; c < 4; c++) {
#pragma unroll
            for (int p = 0; p < 4; p++) {
                float vlo = lo_f(acc[p][c]);
                float vhi = hi_f(acc[p][c]);
                int slo = 2 * p, shi = 2 * p + 1;
                if (vlo > best[slo]) { best[slo] = vlo; bestj[slo] = jbase + c; }
                if (vhi > best[shi]) { best[shi] = vhi; bestj[shi] = jbase + c; }
            }
        }
    }

    // Cross-lane argmax reduce (tie-break: smaller index), then global merge.
#pragma unroll
    for (int i = 0; i < 8; i++) {
        float v  = best[i];
        int   bj = bestj[i];
#pragma unroll
        for (int off = 16; off > 0; off >>= 1) {
            float v2 = __shfl_xor_sync(0xFFFFFFFFu, v, off);
            int   j2 = __shfl_xor_sync(0xFFFFFFFFu, bj, off);
            if (v2 > v || (v2 == v && j2 < bj)) { v = v2; bj = j2; }
        }
        if (lane == 0)
            atomicMax(&g_best[m0 + 8 * sy + i], enc_best(v, bj));
    }
}

// Merge results: gather quantize vector, write index + per-row MSE.
__global__ void combine_kernel(const float* __restrict__ A,
                               const float* __restrict__ Bm,
                               float* __restrict__ out) {
    const int w = threadIdx.x >> 5, lane = threadIdx.x & 31;
    const int s = blockIdx.x * 8 + w;
    const int j = (int)(unsigned)(~(unsigned)g_best[s]);
    float sum = 0.f;
#pragma unroll
    for (int r = 0; r < 4; r++) {
        const int d = lane + r * 32;
        float q = __ldg(&Bm[d * N_EMBED + j]);
        out[s * DIM + d] = q;
        float x = A[s * DIM + d];
        float t = x - q;
        sum += t * t;
    }
#pragma unroll
    for (int off = 16; off > 0; off >>= 1)
        sum += __shfl_xor_sync(0xFFFFFFFFu, sum, off);
    if (lane == 0) {
        out[N_SAMPLES * DIM + s] = (float)j;
        out[N_SAMPLES * (DIM + 1) + s] = sum * (1.0f / DIM);
    }
}

extern "C" void kernel_launch(void* const* d_in, const int* in_sizes, int n_in,
                              void* d_out, int out_size) {
    const float* A  = (const float*)d_in[0];   // inputs [8192,128]
    const float* Bm = (const float*)d_in[1];   // cluster_mean [128,10000]
    if (n_in >= 2 && in_sizes[0] == DIM * N_EMBED) {  // defensive order check
        const float* t = A; A = Bm; Bm = t;
    }
    float* out = (float*)d_out;

    cnorm_kernel<<<N_EMBED_PAD / 256, 256>>>(Bm);

    const int smem_bytes = (DIM * TM + 3 * DIM * TN) * (int)sizeof(float); // 224KB
    static int attr_set = 0;
    if (!attr_set) {
        cudaFuncSetAttribute(quantize_kernel,
                             cudaFuncAttributeMaxDynamicSharedMemorySize, smem_bytes);
        attr_set = 1;
    }
    quantize_kernel<<<128 * NSLICE, THREADS, smem_bytes>>>(A, Bm);
    combine_kernel<<<N_SAMPLES / 8, 256>>>(A, Bm, out);
}

// round 5
// speedup vs baseline: 1.3147x; 1.0325x over previous
#include <cuda_runtime.h>
#include <float.h>
#include <stdint.h>

#define N_SAMPLES 8192
#define DIM 128
#define N_EMBED 10000
#define N_EMBED_PAD 10240
#define TN 128
#define TM 128
#define THREADS 256
#define NSLICE 16
#define SLICE_W 640           // clusters per slice
#define NCH 5                 // chunks of TN per slice

typedef unsigned long long u64;

// Padded cluster norms; entries >= N_EMBED are -1e30 so they never win argmax.
__device__ float g_cnorm[N_EMBED_PAD];
// Per-sample packed (encoded_val << 32 | ~j); atomicMax-merged across slices.
__device__ u64 g_best[N_SAMPLES];

// 160 blocks x 256 threads: 64 j's per block, 4-way d-split + smem reduce.
__global__ void cnorm_kernel(const float* __restrict__ cm) {
    __shared__ float red[4][64];
    const int tid = threadIdx.x;
    const int jl  = tid & 63;
    const int dc  = tid >> 6;            // 0..3 -> d range [32*dc, 32*dc+32)
    const int j   = blockIdx.x * 64 + jl;

    const int gid = blockIdx.x * 256 + tid;
    if (gid < N_SAMPLES) g_best[gid] = 0ull;

    float s = 0.f;
    if (j < N_EMBED) {
#pragma unroll 8
        for (int dd = 0; dd < 32; dd++) {
            float v = cm[(dc * 32 + dd) * N_EMBED + j];
            s += v * v;
        }
    }
    red[dc][jl] = s;
    __syncthreads();
    if (dc == 0) {
        float t = red[0][jl] + red[1][jl] + red[2][jl] + red[3][jl];
        g_cnorm[j] = (j < N_EMBED) ? t : -1e30f;
    }
}

__device__ __forceinline__ void fma2(u64& d, u64 a, u64 b) {
    asm("fma.rn.f32x2 %0, %1, %2, %0;" : "+l"(d) : "l"(a), "l"(b));
}
__device__ __forceinline__ u64 dup2(float v) {
    u64 r; asm("mov.b64 %0, {%1, %1};" : "=l"(r) : "f"(v)); return r;
}
__device__ __forceinline__ float lo_f(u64 v) { return __uint_as_float((unsigned)v); }
__device__ __forceinline__ float hi_f(u64 v) { return __uint_as_float((unsigned)(v >> 32)); }
__device__ __forceinline__ unsigned smem_u32(const void* p) {
    return (unsigned)__cvta_generic_to_shared(p);
}
__device__ __forceinline__ void cp16(unsigned dst, const void* src, int sz) {
    asm volatile("cp.async.cg.shared.global [%0], [%1], 16, %2;"
                 :: "r"(dst), "l"(src), "r"(sz));
}
// Order-preserving encode: larger val -> larger u64; equal val -> smaller j wins.
__device__ __forceinline__ u64 enc_best(float v, int j) {
    unsigned b = __float_as_uint(v);
    b = ((int)b < 0) ? ~b : (b | 0x80000000u);
    return ((u64)b << 32) | (unsigned)(~j);
}

// Fused GEMM(-2x.c, biased by |c|^2) + argmax. One (m-tile, j-slice) per CTA.
// Warp tile: 16 samples x 4 cols; block: 128 samples x 128 cols.
__global__ __launch_bounds__(THREADS, 1)
void quantize_kernel(const float* __restrict__ A,
                     const float* __restrict__ Bm) {
    extern __shared__ float smf[];
    float* As = smf;                 // [DIM][TM]  transposed, holds -2*x   64KB
    float* Bs = smf + DIM * TM;      // 2 x [DIM][TN] ring                 128KB

    const int tid  = threadIdx.x;
    const int lane = tid & 31;
    const int sy   = tid >> 5;       // warp -> 16-sample group
    const int mt   = blockIdx.x & 63;
    const int sl   = blockIdx.x >> 6;
    const int m0   = mt * TM;
    const int j00  = sl * SLICE_W;

    auto issueB = [&](int t) {
        const int j0 = j00 + t * TN;
        float* dst = Bs + (t & 1) * DIM * TN;
        for (int i = tid; i < DIM * (TN / 4); i += THREADS) {  // 16 iters
            int r  = i >> 5;        // 0..127
            int c4 = i & 31;        // 0..31
            int j  = j0 + 4 * c4;
            const float* src = (j < N_EMBED) ? (Bm + (size_t)r * N_EMBED + j) : Bm;
            cp16(smem_u32(dst + r * TN + 4 * c4), src, (j < N_EMBED) ? 16 : 0);
        }
        asm volatile("cp.async.commit_group;");
    };

    // Start B streaming first so it overlaps the A transpose below.
    issueB(0);
    issueB(1);

    // A tile: transpose into smem with -2 folded in.
    for (int i = tid; i < TM * (DIM / 4); i += THREADS) {  // 16 iters
        int k4 = i >> 7;             // 0..31
        int m  = i & 127;            // 0..127
        float4 v = *(const float4*)&A[(m0 + m) * DIM + 4 * k4];
        As[(4 * k4 + 0) * TM + m] = -2.f * v.x;
        As[(4 * k4 + 1) * TM + m] = -2.f * v.y;
        As[(4 * k4 + 2) * TM + m] = -2.f * v.z;
        As[(4 * k4 + 3) * TM + m] = -2.f * v.w;
    }

    float best[16];
    int   bestj[16];
#pragma unroll
    for (int i = 0; i < 16; i++) { best[i] = -FLT_MAX; bestj[i] = 0; }

    const float* Ap = As + 16 * sy;  // warp-uniform -> broadcast LDS

    for (int t = 0; t < NCH; t++) {
        if (t < NCH - 1) asm volatile("cp.async.wait_group 1;");
        else             asm volatile("cp.async.wait_group 0;");
        __syncthreads();             // chunk t resident; As complete (t==0)

        const float* Bp = Bs + (t & 1) * DIM * TN + 4 * lane;
        const int jbase = j00 + t * TN + 4 * lane;

        // acc starts at |c_j|^2 (same for both packed samples of a pair).
        float4 cn4 = *(const float4*)&g_cnorm[jbase];
        u64 cc[4] = {dup2(cn4.x), dup2(cn4.y), dup2(cn4.z), dup2(cn4.w)};
        u64 acc[8][4];
#pragma unroll
        for (int p = 0; p < 8; p++)
#pragma unroll
            for (int c = 0; c < 4; c++) acc[p][c] = cc[c];

#pragma unroll 4
        for (int k = 0; k < DIM; k++) {
            const ulonglong2* ap = (const ulonglong2*)(Ap + k * TM);
            ulonglong2 aa0 = ap[0];   // sample pairs (0,1),(2,3)
            ulonglong2 aa1 = ap[1];   // (4,5),(6,7)
            ulonglong2 aa2 = ap[2];   // (8,9),(10,11)
            ulonglong2 aa3 = ap[3];   // (12,13),(14,15)
            float4 b4 = *(const float4*)(Bp + k * TN);
            u64 b0 = dup2(b4.x), b1 = dup2(b4.y), b2 = dup2(b4.z), b3 = dup2(b4.w);
            u64 a[8] = {aa0.x, aa0.y, aa1.x, aa1.y, aa2.x, aa2.y, aa3.x, aa3.y};
#pragma unroll
            for (int p = 0; p < 8; p++) {
                fma2(acc[p][0], a[p], b0);
                fma2(acc[p][1], a[p], b1);
                fma2(acc[p][2], a[p], b2);
                fma2(acc[p][3], a[p], b3);
            }
        }

        // Running argmax. Ascending j + strict '>' keeps first-occurrence.
#pragma unroll
        for (int c = 0; c < 4; c++) {
#pragma unroll
            for (int p = 0; p < 8; p++) {
                float vlo = lo_f(acc[p][c]);
                float vhi = hi_f(acc[p][c]);
                int slo = 2 * p, shi = 2 * p + 1;
                if (vlo > best[slo]) { best[slo] = vlo; bestj[slo] = jbase + c; }
                if (vhi > best[shi]) { best[shi] = vhi; bestj[shi] = jbase + c; }
            }
        }

        __syncthreads();             // all warps done with slot (t&1)
        if (t + 2 < NCH) issueB(t + 2);
    }

    // Cross-lane argmax reduce (tie-break: smaller index), then global merge.
#pragma unroll
    for (int i = 0; i < 16; i++) {
        float v  = best[i];
        int   bj = bestj[i];
#pragma unroll
        for (int off = 16; off > 0; off >>= 1) {
            float v2 = __shfl_xor_sync(0xFFFFFFFFu, v, off);
            int   j2 = __shfl_xor_sync(0xFFFFFFFFu, bj, off);
            if (v2 > v || (v2 == v && j2 < bj)) { v = v2; bj = j2; }
        }
        if (lane == 0)
            atomicMax(&g_best[m0 + 16 * sy + i], enc_best(v, bj));
    }
}

// Merge results: gather quantize vector, write index + per-row MSE.
__global__ void combine_kernel(const float* __restrict__ A,
                               const float* __restrict__ Bm,
                               float* __restrict__ out) {
    const int w = threadIdx.x >> 5, lane = threadIdx.x & 31;
    const int s = blockIdx.x * 8 + w;
    const int j = (int)(unsigned)(~(unsigned)g_best[s]);
    float sum = 0.f;
#pragma unroll
    for (int r = 0; r < 4; r++) {
        const int d = lane + r * 32;
        float q = __ldg(&Bm[d * N_EMBED + j]);
        out[s * DIM + d] = q;
        float x = A[s * DIM + d];
        float t = x - q;
        sum += t * t;
    }
#pragma unroll
    for (int off = 16; off > 0; off >>= 1)
        sum += __shfl_xor_sync(0xFFFFFFFFu, sum, off);
    if (lane == 0) {
        out[N_SAMPLES * DIM + s] = (float)j;
        out[N_SAMPLES * (DIM + 1) + s] = sum * (1.0f / DIM);
    }
}

extern "C" void kernel_launch(void* const* d_in, const int* in_sizes, int n_in,
                              void* d_out, int out_size) {
    const float* A  = (const float*)d_in[0];   // inputs [8192,128]
    const float* Bm = (const float*)d_in[1];   // cluster_mean [128,10000]
    if (n_in >= 2 && in_sizes[0] == DIM * N_EMBED) {  // defensive order check
        const float* t = A; A = Bm; Bm = t;
    }
    float* out = (float*)d_out;

    cnorm_kernel<<<N_EMBED_PAD / 64, 256>>>(Bm);

    const int smem_bytes = (DIM * TM + 2 * DIM * TN) * (int)sizeof(float); // 192KB
    static int attr_set = 0;
    if (!attr_set) {
        cudaFuncSetAttribute(quantize_kernel,
                             cudaFuncAttributeMaxDynamicSharedMemorySize, smem_bytes);
        attr_set = 1;
    }
    quantize_kernel<<<64 * NSLICE, THREADS, smem_bytes>>>(A, Bm);
    combine_kernel<<<N_SAMPLES / 8, 256>>>(A, Bm, out);
}